// round 15
// baseline (speedup 1.0000x reference)
#include <cuda_runtime.h>
#include <math.h>
#include <stdint.h>

// Problem dims
#define BB   32
#define TT   14
#define MM   2048
#define QD   768
#define KVD  1024
#define HH   12
#define HD   64
#define FFD  3072
#define BT_ROWS 448   // B*T
#define RH      168   // T*H
#define NATTN (BB*TT*HH*MM)   // 11010048

// -------- scratch (device globals; no allocation allowed) --------
__device__ float g_Q  [BT_ROWS*QD];
__device__ float g_qb [BT_ROWS*HH];
__device__ float g_Qt [BT_ROWS*HH*KVD];
__device__ float g_ctx[BT_ROWS*HH*KVD];
__device__ float g_ao [BT_ROWS*QD];
__device__ float g_x  [BT_ROWS*QD];
__device__ float g_hid[BT_ROWS*FFD];
__device__ float g_y  [BT_ROWS*QD];

__device__ __forceinline__ uint32_t f2tf_u(float f) {
    uint32_t r;
    asm("cvt.rna.tf32.f32 %0, %1;" : "=r"(r) : "f"(f));
    return r;
}
__device__ __forceinline__ float f2tf_f(float f) {
    return __uint_as_float(f2tf_u(f));
}

__device__ __forceinline__ void cp16(uint32_t dst, const float* src, bool pred) {
    asm volatile("cp.async.cg.shared.global [%0], [%1], 16, %2;"
                 :: "r"(dst), "l"(src), "r"(pred ? 16 : 0));
}
__device__ __forceinline__ void cp_commit() {
    asm volatile("cp.async.commit_group;" ::: "memory");
}
__device__ __forceinline__ void cp_wait0() {
    asm volatile("cp.async.wait_group 0;" ::: "memory");
}
__device__ __forceinline__ void cp_wait1() {
    asm volatile("cp.async.wait_group 1;" ::: "memory");
}

// ============================================================================
// TF32 tensor-core GEMM, BK=32, cp.async pipeline, per-call-site tile/depth.
//   Warp tile WM x WN (WN in {32, 64}); bigger tiles cut smem fragment
//   traffic per MMA: 4096*(1/WM + 1/WN) B/MMA.
//   STG:  2 = double buffer (wait0, dist 1), 3 = triple buffer (wait1, dist 2)
//   MINB: min-blocks residency hint (3 -> interleave CTA phases)
//   C[m,n] = sum_k A[m,k] * B'[k,n]  (per batch z)
//   TRB=false: B'[k,n] = Bp[k*ldb + n]   ("NN")
//   TRB=true : B'[k,n] = Bp[n*ldb + k]   ("NT")
// EPI: 0=none, 1=+colbias, 2=relu(+colbias), 3=(acc+rowbias)*scale
// CVTA/CVTB: round fragments to tf32-nearest in-loop. RND: round outputs.
// K%32==0, N%BN==0; M guarded.
// ============================================================================
template<int BM, int BN, int WM, int WN, bool TRB, int EPI,
         bool CVTA, bool CVTB, bool RND, int STG, int MINB>
__global__ void __launch_bounds__((BM/WM)*(BN/WN)*32, MINB)
mma_gemm(const float* __restrict__ A, int lda, long aBS,
         const float* __restrict__ Bp, int ldb, long bBS,
         float* __restrict__ C, int ldc, long cBS,
         const float* __restrict__ bias, int biasBS,
         int Mrows, float scale, int K)
{
    constexpr int NWARP = (BM/WM)*(BN/WN);
    constexpr int NTH   = NWARP*32;
    constexpr int AST   = BM*36;                    // floats per A stage
    constexpr int BST   = TRB ? BN*36 : 32*(BN+8);  // floats per B stage
    constexpr int MC    = WM/16;                    // 16-row chunks per warp
    constexpr int NC    = WN/8;                     // 8-col chunks per warp

    extern __shared__ float smem[];
    float* As = smem;                               // STG stages
    float* Bs = smem + STG*AST;
    uint32_t s_as = (uint32_t)__cvta_generic_to_shared(As);
    uint32_t s_bs = (uint32_t)__cvta_generic_to_shared(Bs);

    const int bz = blockIdx.z;
    A  += (long)bz * aBS;
    Bp += (long)bz * bBS;
    C  += (long)bz * cBS;
    if (bias) bias += (long)bz * biasBS;

    const int row0 = blockIdx.y * BM;
    const int col0 = blockIdx.x * BN;
    const int tid  = threadIdx.x;
    const int lane = tid & 31;
    const int warp = tid >> 5;
    const int wm   = warp / (BN/WN);
    const int wn   = warp % (BN/WN);
    const int g    = lane >> 2;
    const int tg   = lane & 3;

    auto stage_load = [&](int st, int k0) {
#pragma unroll
        for (int it = 0; it < (BM*8)/NTH; it++) {
            int i = tid + it*NTH;
            int m = i >> 3, q = i & 7;
            cp16(s_as + (uint32_t)(st*AST + m*36 + q*4)*4,
                 A + (long)(row0+m)*lda + k0 + q*4,
                 (row0 + m) < Mrows);
        }
        if (TRB) {
#pragma unroll
            for (int it = 0; it < (BN*8)/NTH; it++) {
                int i = tid + it*NTH;
                int n = i >> 3, q = i & 7;
                cp16(s_bs + (uint32_t)(st*BST + n*36 + q*4)*4,
                     Bp + (long)(col0+n)*ldb + k0 + q*4, true);
            }
        } else {
#pragma unroll
            for (int it = 0; it < (32*(BN/4))/NTH; it++) {
                int i = tid + it*NTH;
                int k = i / (BN/4), nq = i % (BN/4);
                cp16(s_bs + (uint32_t)(st*BST + k*(BN+8) + nq*4)*4,
                     Bp + (long)(k0+k)*ldb + col0 + nq*4, true);
            }
        }
    };

    float acc[MC][NC][4];
#pragma unroll
    for (int i = 0; i < MC; i++)
#pragma unroll
        for (int j = 0; j < NC; j++)
#pragma unroll
            for (int r = 0; r < 4; r++) acc[i][j][r] = 0.f;

    const int nk = K/32;
    stage_load(0, 0);
    cp_commit();
    if (STG == 3) {
        if (nk > 1) stage_load(1, 32);
        cp_commit();
    }

    for (int t = 0; t < nk; t++) {
        if (STG == 3) cp_wait1(); else cp_wait0();
        __syncthreads();
        if (STG == 3) {
            if (t + 2 < nk) stage_load((t+2)%3, (t+2)*32);
            cp_commit();
        } else {
            if (t + 1 < nk) { stage_load((t+1)&1, (t+1)*32); cp_commit(); }
        }

        const float* As_s = As + (STG == 3 ? (t%3) : (t&1))*AST;
        const float* Bs_s = Bs + (STG == 3 ? (t%3) : (t&1))*BST;

#pragma unroll
        for (int kk = 0; kk < 4; kk++) {
            uint32_t a[MC][4];
#pragma unroll
            for (int i = 0; i < MC; i++) {
                int r = wm*WM + i*16;
                float a0 = As_s[(r+g  )*36 + kk*8 + tg  ];
                float a1 = As_s[(r+g+8)*36 + kk*8 + tg  ];
                float a2 = As_s[(r+g  )*36 + kk*8 + tg+4];
                float a3 = As_s[(r+g+8)*36 + kk*8 + tg+4];
                a[i][0] = CVTA ? f2tf_u(a0) : __float_as_uint(a0);
                a[i][1] = CVTA ? f2tf_u(a1) : __float_as_uint(a1);
                a[i][2] = CVTA ? f2tf_u(a2) : __float_as_uint(a2);
                a[i][3] = CVTA ? f2tf_u(a3) : __float_as_uint(a3);
            }
            uint32_t b[NC][2];
#pragma unroll
            for (int j = 0; j < NC; j++) {
                int n = wn*WN + j*8 + g;
                float b0, b1;
                if (TRB) {
                    b0 = Bs_s[n*36 + kk*8 + tg  ];
                    b1 = Bs_s[n*36 + kk*8 + tg+4];
                } else {
                    b0 = Bs_s[(kk*8 + tg  )*(BN+8) + n];
                    b1 = Bs_s[(kk*8 + tg+4)*(BN+8) + n];
                }
                b[j][0] = CVTB ? f2tf_u(b0) : __float_as_uint(b0);
                b[j][1] = CVTB ? f2tf_u(b1) : __float_as_uint(b1);
            }
#pragma unroll
            for (int i = 0; i < MC; i++)
#pragma unroll
                for (int j = 0; j < NC; j++) {
                    asm volatile(
                        "mma.sync.aligned.m16n8k8.row.col.f32.tf32.tf32.f32 "
                        "{%0,%1,%2,%3}, {%4,%5,%6,%7}, {%8,%9}, {%0,%1,%2,%3};"
                        : "+f"(acc[i][j][0]), "+f"(acc[i][j][1]),
                          "+f"(acc[i][j][2]), "+f"(acc[i][j][3])
                        : "r"(a[i][0]), "r"(a[i][1]), "r"(a[i][2]), "r"(a[i][3]),
                          "r"(b[j][0]), "r"(b[j][1]));
                }
        }
    }

    // ---- epilogue ----
#pragma unroll
    for (int i = 0; i < MC; i++) {
        int r0 = row0 + wm*WM + i*16 + g;
#pragma unroll
        for (int rr = 0; rr < 2; rr++) {
            int gm = r0 + rr*8;
            if (gm >= Mrows) continue;
            float rb = (EPI == 3) ? bias[gm] : 0.f;
#pragma unroll
            for (int j = 0; j < NC; j++) {
                int cn = col0 + wn*WN + j*8 + 2*tg;
                float v0 = acc[i][j][rr*2 + 0];
                float v1 = acc[i][j][rr*2 + 1];
                if (EPI == 1)      { v0 += bias[cn]; v1 += bias[cn+1]; }
                else if (EPI == 2) { v0 = fmaxf(v0 + bias[cn], 0.f);
                                     v1 = fmaxf(v1 + bias[cn+1], 0.f); }
                else if (EPI == 3) { v0 = (v0 + rb) * scale; v1 = (v1 + rb) * scale; }
                if (RND) { v0 = f2tf_f(v0); v1 = f2tf_f(v1); }
                *(float2*)(C + (long)gm*ldc + cn) = make_float2(v0, v1);
            }
        }
    }
}

// qb[bt,h] = sum_d Q[bt, h*64+d] * bK[h*64+d]
__global__ void qb_k(const float* __restrict__ Q, const float* __restrict__ bK,
                     float* __restrict__ qb)
{
    int idx = blockIdx.x*blockDim.x + threadIdx.x;
    if (idx >= BT_ROWS*HH) return;
    int bt = idx / HH, h = idx % HH;
    const float* q  = Q  + (long)bt*QD + h*HD;
    const float* bk = bK + h*HD;
    float s = 0.f;
#pragma unroll 8
    for (int d = 0; d < HD; d++) s = fmaf(q[d], bk[d], s);
    qb[idx] = s;
}

// in-place softmax over rows of length 2048; output rounded to tf32-nearest
__global__ void softmax_k(float* __restrict__ attn)
{
    float* p = attn + (long)blockIdx.x * MM;
    int tid = threadIdx.x;
    int lane = tid & 31, w = tid >> 5;
    __shared__ float red[8];

    float v[8];
    float mx = -1e30f;
#pragma unroll
    for (int i = 0; i < 8; i++) { v[i] = p[tid + 256*i]; mx = fmaxf(mx, v[i]); }
#pragma unroll
    for (int o = 16; o; o >>= 1) mx = fmaxf(mx, __shfl_xor_sync(0xffffffffu, mx, o));
    if (lane == 0) red[w] = mx;
    __syncthreads();
    mx = red[0];
#pragma unroll
    for (int i = 1; i < 8; i++) mx = fmaxf(mx, red[i]);
    __syncthreads();

    float s = 0.f;
#pragma unroll
    for (int i = 0; i < 8; i++) { v[i] = __expf(v[i] - mx); s += v[i]; }
#pragma unroll
    for (int o = 16; o; o >>= 1) s += __shfl_xor_sync(0xffffffffu, s, o);
    if (lane == 0) red[w] = s;
    __syncthreads();
    float tot = 0.f;
#pragma unroll
    for (int i = 0; i < 8; i++) tot += red[i];

    float inv = 1.f / tot;
#pragma unroll
    for (int i = 0; i < 8; i++) p[tid + 256*i] = f2tf_f(v[i] * inv);
}

// out[row,:] = LN(a[row,:] + b[row,:]) * g + be   (row length 768)
__global__ void ln_k(const float* __restrict__ a, const float* __restrict__ b,
                     const float* __restrict__ g, const float* __restrict__ be,
                     float* __restrict__ out, int rnd)
{
    long row = blockIdx.x;
    int tid = threadIdx.x;
    int lane = tid & 31, w = tid >> 5;
    const float* pa = a + row*QD;
    const float* pb = b + row*QD;
    __shared__ float red[8];

    float v[3];
    float s = 0.f;
#pragma unroll
    for (int i = 0; i < 3; i++) { v[i] = pa[tid + 256*i] + pb[tid + 256*i]; s += v[i]; }
#pragma unroll
    for (int o = 16; o; o >>= 1) s += __shfl_xor_sync(0xffffffffu, s, o);
    if (lane == 0) red[w] = s;
    __syncthreads();
    float tot = 0.f;
#pragma unroll
    for (int i = 0; i < 8; i++) tot += red[i];
    float mu = tot * (1.f/768.f);
    __syncthreads();

    float sq = 0.f;
#pragma unroll
    for (int i = 0; i < 3; i++) { float d = v[i] - mu; sq = fmaf(d, d, sq); }
#pragma unroll
    for (int o = 16; o; o >>= 1) sq += __shfl_xor_sync(0xffffffffu, sq, o);
    if (lane == 0) red[w] = sq;
    __syncthreads();
    float vtot = 0.f;
#pragma unroll
    for (int i = 0; i < 8; i++) vtot += red[i];
    float inv = rsqrtf(vtot * (1.f/768.f) + 1e-5f);

#pragma unroll
    for (int i = 0; i < 3; i++) {
        int c = tid + 256*i;
        float o = (v[i] - mu) * inv * g[c] + be[c];
        out[row*QD + c] = rnd ? f2tf_f(o) : o;
    }
}

// smem byte sizes per instantiation
template<int BM, int BN, bool TRB, int STG>
constexpr int smem_bytes() {
    return STG * (BM*36 + (TRB ? BN*36 : 32*(BN+8))) * 4;
}

extern "C" void kernel_launch(void* const* d_in, const int* in_sizes, int n_in,
                              void* d_out_v, int out_size)
{
    const float* expert = (const float*)d_in[0];
    const float* kv     = (const float*)d_in[1];
    const float* WQ  = (const float*)d_in[2];
    const float* bQ  = (const float*)d_in[3];
    const float* WK  = (const float*)d_in[4];
    const float* bK  = (const float*)d_in[5];
    const float* WV  = (const float*)d_in[6];
    const float* bV  = (const float*)d_in[7];
    const float* W1  = (const float*)d_in[8];
    const float* b1  = (const float*)d_in[9];
    const float* W2  = (const float*)d_in[10];
    const float* b2  = (const float*)d_in[11];
    const float* g1  = (const float*)d_in[12];
    const float* be1 = (const float*)d_in[13];
    const float* g2  = (const float*)d_in[14];
    const float* be2 = (const float*)d_in[15];

    float* out   = (float*)d_out_v;
    float* attnw = out + ((long)out_size - (long)NATTN);

    float *Q, *qb, *Qt, *ctx, *ao, *x, *hid, *y;
    cudaGetSymbolAddress((void**)&Q,   g_Q);
    cudaGetSymbolAddress((void**)&qb,  g_qb);
    cudaGetSymbolAddress((void**)&Qt,  g_Qt);
    cudaGetSymbolAddress((void**)&ctx, g_ctx);
    cudaGetSymbolAddress((void**)&ao,  g_ao);
    cudaGetSymbolAddress((void**)&x,   g_x);
    cudaGetSymbolAddress((void**)&hid, g_hid);
    cudaGetSymbolAddress((void**)&y,   g_y);

    // 1) Q proj (NN, warp 32x32, 3-stage, MINB 2): Q -> RND
    cudaFuncSetAttribute(mma_gemm<32,128,32,32,false,1,true,true,true,3,2>,
        cudaFuncAttributeMaxDynamicSharedMemorySize, smem_bytes<32,128,false,3>());
    mma_gemm<32,128,32,32,false,1,true,true,true,3,2>
        <<<dim3(QD/128, 1, TT), 128, smem_bytes<32,128,false,3>()>>>(
        expert, TT*QD, (long)QD,
        WQ, QD, (long)QD*QD,
        Q, TT*QD, (long)QD,
        bQ, QD, BB, 1.f, QD);

    // 2) qb = per-head Q . bK
    qb_k<<<(BT_ROWS*HH)/256, 256>>>(Q, bK, qb);

    // 3) Qt = Q @ WK^T (NT, nk=2, warp 64x32, 2-stage, MINB 3); Qt -> RND
    cudaFuncSetAttribute(mma_gemm<64,128,64,32,true,0,false,true,true,2,3>,
        cudaFuncAttributeMaxDynamicSharedMemorySize, smem_bytes<64,128,true,2>());
    mma_gemm<64,128,64,32,true,0,false,true,true,2,3>
        <<<dim3(KVD/128, 7, HH), 128, smem_bytes<64,128,true,2>()>>>(
        Q, QD, (long)HD,
        WK, QD, (long)HD,
        Qt, HH*KVD, (long)KVD,
        nullptr, 0, BT_ROWS, 1.f, HD);

    // 4) scores = (Qt . kv + qb)/8  (NT, warp 64x64 -> 128 B/MMA, 2-stage, MINB 3)
    cudaFuncSetAttribute(mma_gemm<64,128,64,64,true,3,false,true,false,2,3>,
        cudaFuncAttributeMaxDynamicSharedMemorySize, smem_bytes<64,128,true,2>());
    mma_gemm<64,128,64,64,true,3,false,true,false,2,3>
        <<<dim3(MM/128, 3, BB), 64, smem_bytes<64,128,true,2>()>>>(
        Qt, KVD, (long)RH*KVD,
        kv, KVD, (long)MM*KVD,
        attnw, MM, (long)RH*MM,
        qb, RH, RH, 0.125f, KVD);

    // 5) softmax over m (in place; rounds attnw to tf32-nearest)
    softmax_k<<<BB*TT*HH, 256>>>(attnw);

    // 6) ctx = attnw . kv  (NN, warp 64x64, 2-stage, MINB 3); ctx -> RND
    cudaFuncSetAttribute(mma_gemm<64,128,64,64,false,0,false,true,true,2,3>,
        cudaFuncAttributeMaxDynamicSharedMemorySize, smem_bytes<64,128,false,2>());
    mma_gemm<64,128,64,64,false,0,false,true,true,2,3>
        <<<dim3(KVD/128, 3, BB), 64, smem_bytes<64,128,false,2>()>>>(
        attnw, MM, (long)RH*MM,
        kv, KVD, (long)MM*KVD,
        ctx, KVD, (long)RH*KVD,
        nullptr, 0, RH, 1.f, MM);

    // 7) attn_out = ctx @ WV + bV  (small; warp 64x32, 3-stage, MINB 2)
    cudaFuncSetAttribute(mma_gemm<64,64,64,32,false,1,false,true,false,3,2>,
        cudaFuncAttributeMaxDynamicSharedMemorySize, smem_bytes<64,64,false,3>());
    mma_gemm<64,64,64,32,false,1,false,true,false,3,2>
        <<<dim3(1, 7, HH), 64, smem_bytes<64,64,false,3>()>>>(
        ctx, HH*KVD, (long)KVD,
        WV, QD, (long)HD,
        ao, QD, (long)HD,
        bV, HD, BT_ROWS, 1.f, KVD);

    // 8) x = LN1(expert + attn_out), rounded (x feeds FF1 as A)
    ln_k<<<BT_ROWS, 256>>>(expert, ao, g1, be1, x, 1);

    // 9) hidden = relu(x @ W1 + b1)  (NN, warp 64x32, 3-stage, MINB 2); hid -> RND
    cudaFuncSetAttribute(mma_gemm<64,128,64,32,false,2,false,true,true,3,2>,
        cudaFuncAttributeMaxDynamicSharedMemorySize, smem_bytes<64,128,false,3>());
    mma_gemm<64,128,64,32,false,2,false,true,true,3,2>
        <<<dim3(FFD/128, 7, 1), 128, smem_bytes<64,128,false,3>()>>>(
        x, QD, 0,
        W1, FFD, 0,
        hid, FFD, 0,
        b1, 0, BT_ROWS, 1.f, QD);

    // 10) y = hid @ W2 + b2  (NN, warp 64x32, 3-stage, MINB 2)
    cudaFuncSetAttribute(mma_gemm<64,128,64,32,false,1,false,true,false,3,2>,
        cudaFuncAttributeMaxDynamicSharedMemorySize, smem_bytes<64,128,false,3>());
    mma_gemm<64,128,64,32,false,1,false,true,false,3,2>
        <<<dim3(QD/128, 7, 1), 128, smem_bytes<64,128,false,3>()>>>(
        hid, FFD, 0,
        W2, QD, 0,
        y, QD, 0,
        b2, 0, BT_ROWS, 1.f, FFD);

    // 11) out = LN2(x + y), full precision (checked output)
    ln_k<<<BT_ROWS, 256>>>(x, y, g2, be2, out, 0);
}

// round 16
// speedup vs baseline: 1.0652x; 1.0652x over previous
#include <cuda_runtime.h>
#include <math.h>
#include <stdint.h>

// Problem dims
#define BB   32
#define TT   14
#define MM   2048
#define QD   768
#define KVD  1024
#define HH   12
#define HD   64
#define FFD  3072
#define BT_ROWS 448   // B*T
#define RH      168   // T*H
#define NATTN (BB*TT*HH*MM)   // 11010048

// -------- scratch (device globals; no allocation allowed) --------
__device__ float g_Q  [BT_ROWS*QD];
__device__ float g_qb [BT_ROWS*HH];
__device__ float g_Qt [BT_ROWS*HH*KVD];
__device__ float g_ctx[BT_ROWS*HH*KVD];
__device__ float g_ao [BT_ROWS*QD];
__device__ float g_x  [BT_ROWS*QD];
__device__ float g_hid[BT_ROWS*FFD];
__device__ float g_y  [BT_ROWS*QD];

__device__ __forceinline__ uint32_t f2tf_u(float f) {
    uint32_t r;
    asm("cvt.rna.tf32.f32 %0, %1;" : "=r"(r) : "f"(f));
    return r;
}
__device__ __forceinline__ float f2tf_f(float f) {
    return __uint_as_float(f2tf_u(f));
}

// FMA-pipe exp for x <= 0 (softmax): exp(x) = 2^(x*log2e).
// rint via +2^23 magic constant (rn intrinsics block fast-math folding),
// degree-5 Taylor for 2^f on [-0.5, 0.5] (~2e-6 rel), exponent spliced
// into the float bits. ~8 FMA + 2 ALU ops vs 1 MUFU (chip MUFU-rate-bound).
__device__ __forceinline__ float fexp(float x) {
    float y = fmaxf(x * 1.4426950408889634f, -126.0f);
    float t  = __fadd_rn(y, 12582912.0f);          // low bits = rint(y) + 2^22
    float fi = __fsub_rn(t, 12582912.0f);          // rint(y)
    float f  = __fsub_rn(y, fi);                   // [-0.5, 0.5]
    float p =            1.33335581e-3f;
    p = fmaf(p, f, 9.61812911e-3f);
    p = fmaf(p, f, 5.55041087e-2f);
    p = fmaf(p, f, 2.40226507e-1f);
    p = fmaf(p, f, 6.93147181e-1f);
    p = fmaf(p, f, 1.0f);
    // (bits(t) << 23) == rint(y) << 23 (mod 2^32): 2^22 offset overflows out
    uint32_t r = __float_as_uint(p) + (__float_as_uint(t) << 23);
    return __uint_as_float(r);
}

__device__ __forceinline__ void cp16(uint32_t dst, const float* src, bool pred) {
    asm volatile("cp.async.cg.shared.global [%0], [%1], 16, %2;"
                 :: "r"(dst), "l"(src), "r"(pred ? 16 : 0));
}
__device__ __forceinline__ void cp_commit() {
    asm volatile("cp.async.commit_group;" ::: "memory");
}
__device__ __forceinline__ void cp_wait0() {
    asm volatile("cp.async.wait_group 0;" ::: "memory");
}
__device__ __forceinline__ void cp_wait1() {
    asm volatile("cp.async.wait_group 1;" ::: "memory");
}

// ============================================================================
// TF32 tensor-core GEMM, BK=32, cp.async pipeline with per-call-site depth.
//   STG:  2 = double buffer (wait0, dist 1), 3 = triple buffer (wait1, dist 2)
//   MINB: min-blocks residency hint (3 -> interleave CTA phases)
//   C[m,n] = sum_k A[m,k] * B'[k,n]  (per batch z)
//   TRB=false: B'[k,n] = Bp[k*ldb + n]   ("NN")
//   TRB=true : B'[k,n] = Bp[n*ldb + k]   ("NT")
// EPI: 0=none, 1=+colbias, 2=relu(+colbias), 3=(acc+rowbias)*scale
// CVTA/CVTB: round fragments to tf32-nearest in-loop. RND: round outputs.
// Warp tile WM x 32. K%32==0, N%BN==0; M guarded.
// ============================================================================
template<int BM, int BN, int WM, bool TRB, int EPI, bool CVTA, bool CVTB, bool RND,
         int STG, int MINB>
__global__ void __launch_bounds__((BM/WM)*(BN/32)*32, MINB)
mma_gemm(const float* __restrict__ A, int lda, long aBS,
         const float* __restrict__ Bp, int ldb, long bBS,
         float* __restrict__ C, int ldc, long cBS,
         const float* __restrict__ bias, int biasBS,
         int Mrows, float scale, int K)
{
    constexpr int NWARP = (BM/WM)*(BN/32);
    constexpr int NTH   = NWARP*32;
    constexpr int AST   = BM*36;                    // floats per A stage
    constexpr int BST   = TRB ? BN*36 : 32*(BN+8);  // floats per B stage
    constexpr int MC    = WM/16;                    // 16-row chunks per warp

    extern __shared__ float smem[];
    float* As = smem;                               // STG stages
    float* Bs = smem + STG*AST;
    uint32_t s_as = (uint32_t)__cvta_generic_to_shared(As);
    uint32_t s_bs = (uint32_t)__cvta_generic_to_shared(Bs);

    const int bz = blockIdx.z;
    A  += (long)bz * aBS;
    Bp += (long)bz * bBS;
    C  += (long)bz * cBS;
    if (bias) bias += (long)bz * biasBS;

    const int row0 = blockIdx.y * BM;
    const int col0 = blockIdx.x * BN;
    const int tid  = threadIdx.x;
    const int lane = tid & 31;
    const int warp = tid >> 5;
    const int wm   = warp / (BN/32);
    const int wn   = warp % (BN/32);
    const int g    = lane >> 2;
    const int tg   = lane & 3;

    auto stage_load = [&](int st, int k0) {
#pragma unroll
        for (int it = 0; it < (BM*8)/NTH; it++) {
            int i = tid + it*NTH;
            int m = i >> 3, q = i & 7;
            cp16(s_as + (uint32_t)(st*AST + m*36 + q*4)*4,
                 A + (long)(row0+m)*lda + k0 + q*4,
                 (row0 + m) < Mrows);
        }
        if (TRB) {
#pragma unroll
            for (int it = 0; it < (BN*8)/NTH; it++) {
                int i = tid + it*NTH;
                int n = i >> 3, q = i & 7;
                cp16(s_bs + (uint32_t)(st*BST + n*36 + q*4)*4,
                     Bp + (long)(col0+n)*ldb + k0 + q*4, true);
            }
        } else {
#pragma unroll
            for (int it = 0; it < (32*(BN/4))/NTH; it++) {
                int i = tid + it*NTH;
                int k = i / (BN/4), nq = i % (BN/4);
                cp16(s_bs + (uint32_t)(st*BST + k*(BN+8) + nq*4)*4,
                     Bp + (long)(k0+k)*ldb + col0 + nq*4, true);
            }
        }
    };

    float acc[MC][4][4];
#pragma unroll
    for (int i = 0; i < MC; i++)
#pragma unroll
        for (int j = 0; j < 4; j++)
#pragma unroll
            for (int r = 0; r < 4; r++) acc[i][j][r] = 0.f;

    const int nk = K/32;
    stage_load(0, 0);
    cp_commit();
    if (STG == 3) {
        if (nk > 1) stage_load(1, 32);
        cp_commit();
    }

    for (int t = 0; t < nk; t++) {
        if (STG == 3) cp_wait1(); else cp_wait0();
        __syncthreads();
        if (STG == 3) {
            if (t + 2 < nk) stage_load((t+2)%3, (t+2)*32);
            cp_commit();
        } else {
            if (t + 1 < nk) { stage_load((t+1)&1, (t+1)*32); cp_commit(); }
        }

        const float* As_s = As + (STG == 3 ? (t%3) : (t&1))*AST;
        const float* Bs_s = Bs + (STG == 3 ? (t%3) : (t&1))*BST;

#pragma unroll
        for (int kk = 0; kk < 4; kk++) {
            uint32_t a[MC][4];
#pragma unroll
            for (int i = 0; i < MC; i++) {
                int r = wm*WM + i*16;
                float a0 = As_s[(r+g  )*36 + kk*8 + tg  ];
                float a1 = As_s[(r+g+8)*36 + kk*8 + tg  ];
                float a2 = As_s[(r+g  )*36 + kk*8 + tg+4];
                float a3 = As_s[(r+g+8)*36 + kk*8 + tg+4];
                a[i][0] = CVTA ? f2tf_u(a0) : __float_as_uint(a0);
                a[i][1] = CVTA ? f2tf_u(a1) : __float_as_uint(a1);
                a[i][2] = CVTA ? f2tf_u(a2) : __float_as_uint(a2);
                a[i][3] = CVTA ? f2tf_u(a3) : __float_as_uint(a3);
            }
            uint32_t b[4][2];
#pragma unroll
            for (int j = 0; j < 4; j++) {
                int n = wn*32 + j*8 + g;
                float b0, b1;
                if (TRB) {
                    b0 = Bs_s[n*36 + kk*8 + tg  ];
                    b1 = Bs_s[n*36 + kk*8 + tg+4];
                } else {
                    b0 = Bs_s[(kk*8 + tg  )*(BN+8) + n];
                    b1 = Bs_s[(kk*8 + tg+4)*(BN+8) + n];
                }
                b[j][0] = CVTB ? f2tf_u(b0) : __float_as_uint(b0);
                b[j][1] = CVTB ? f2tf_u(b1) : __float_as_uint(b1);
            }
#pragma unroll
            for (int i = 0; i < MC; i++)
#pragma unroll
                for (int j = 0; j < 4; j++) {
                    asm volatile(
                        "mma.sync.aligned.m16n8k8.row.col.f32.tf32.tf32.f32 "
                        "{%0,%1,%2,%3}, {%4,%5,%6,%7}, {%8,%9}, {%0,%1,%2,%3};"
                        : "+f"(acc[i][j][0]), "+f"(acc[i][j][1]),
                          "+f"(acc[i][j][2]), "+f"(acc[i][j][3])
                        : "r"(a[i][0]), "r"(a[i][1]), "r"(a[i][2]), "r"(a[i][3]),
                          "r"(b[j][0]), "r"(b[j][1]));
                }
        }
    }

    // ---- epilogue ----
#pragma unroll
    for (int i = 0; i < MC; i++) {
        int r0 = row0 + wm*WM + i*16 + g;
#pragma unroll
        for (int rr = 0; rr < 2; rr++) {
            int gm = r0 + rr*8;
            if (gm >= Mrows) continue;
            float rb = (EPI == 3) ? bias[gm] : 0.f;
#pragma unroll
            for (int j = 0; j < 4; j++) {
                int cn = col0 + wn*32 + j*8 + 2*tg;
                float v0 = acc[i][j][rr*2 + 0];
                float v1 = acc[i][j][rr*2 + 1];
                if (EPI == 1)      { v0 += bias[cn]; v1 += bias[cn+1]; }
                else if (EPI == 2) { v0 = fmaxf(v0 + bias[cn], 0.f);
                                     v1 = fmaxf(v1 + bias[cn+1], 0.f); }
                else if (EPI == 3) { v0 = (v0 + rb) * scale; v1 = (v1 + rb) * scale; }
                if (RND) { v0 = f2tf_f(v0); v1 = f2tf_f(v1); }
                *(float2*)(C + (long)gm*ldc + cn) = make_float2(v0, v1);
            }
        }
    }
}

// qb[bt,h] = sum_d Q[bt, h*64+d] * bK[h*64+d]
__global__ void qb_k(const float* __restrict__ Q, const float* __restrict__ bK,
                     float* __restrict__ qb)
{
    int idx = blockIdx.x*blockDim.x + threadIdx.x;
    if (idx >= BT_ROWS*HH) return;
    int bt = idx / HH, h = idx % HH;
    const float* q  = Q  + (long)bt*QD + h*HD;
    const float* bk = bK + h*HD;
    float s = 0.f;
#pragma unroll 8
    for (int d = 0; d < HD; d++) s = fmaf(q[d], bk[d], s);
    qb[idx] = s;
}

// in-place softmax over rows of length 2048; FMA-pipe exp (MUFU was the
// chip-level bottleneck: 11M EX2 at 8 cyc/SMSP rt ~= 85us). Output rounded
// to tf32-nearest (attnw feeds the ctx GEMM as a pre-rounded A operand).
__global__ void softmax_k(float* __restrict__ attn)
{
    float* p = attn + (long)blockIdx.x * MM;
    int tid = threadIdx.x;
    int lane = tid & 31, w = tid >> 5;
    __shared__ float red[8];

    float v[8];
    float mx = -1e30f;
#pragma unroll
    for (int i = 0; i < 8; i++) { v[i] = p[tid + 256*i]; mx = fmaxf(mx, v[i]); }
#pragma unroll
    for (int o = 16; o; o >>= 1) mx = fmaxf(mx, __shfl_xor_sync(0xffffffffu, mx, o));
    if (lane == 0) red[w] = mx;
    __syncthreads();
    mx = red[0];
#pragma unroll
    for (int i = 1; i < 8; i++) mx = fmaxf(mx, red[i]);
    __syncthreads();

    float s = 0.f;
#pragma unroll
    for (int i = 0; i < 8; i++) { v[i] = fexp(v[i] - mx); s += v[i]; }
#pragma unroll
    for (int o = 16; o; o >>= 1) s += __shfl_xor_sync(0xffffffffu, s, o);
    if (lane == 0) red[w] = s;
    __syncthreads();
    float tot = 0.f;
#pragma unroll
    for (int i = 0; i < 8; i++) tot += red[i];

    float inv = 1.f / tot;
#pragma unroll
    for (int i = 0; i < 8; i++) p[tid + 256*i] = f2tf_f(v[i] * inv);
}

// out[row,:] = LN(a[row,:] + b[row,:]) * g + be   (row length 768)
__global__ void ln_k(const float* __restrict__ a, const float* __restrict__ b,
                     const float* __restrict__ g, const float* __restrict__ be,
                     float* __restrict__ out, int rnd)
{
    long row = blockIdx.x;
    int tid = threadIdx.x;
    int lane = tid & 31, w = tid >> 5;
    const float* pa = a + row*QD;
    const float* pb = b + row*QD;
    __shared__ float red[8];

    float v[3];
    float s = 0.f;
#pragma unroll
    for (int i = 0; i < 3; i++) { v[i] = pa[tid + 256*i] + pb[tid + 256*i]; s += v[i]; }
#pragma unroll
    for (int o = 16; o; o >>= 1) s += __shfl_xor_sync(0xffffffffu, s, o);
    if (lane == 0) red[w] = s;
    __syncthreads();
    float tot = 0.f;
#pragma unroll
    for (int i = 0; i < 8; i++) tot += red[i];
    float mu = tot * (1.f/768.f);
    __syncthreads();

    float sq = 0.f;
#pragma unroll
    for (int i = 0; i < 3; i++) { float d = v[i] - mu; sq = fmaf(d, d, sq); }
#pragma unroll
    for (int o = 16; o; o >>= 1) sq += __shfl_xor_sync(0xffffffffu, sq, o);
    if (lane == 0) red[w] = sq;
    __syncthreads();
    float vtot = 0.f;
#pragma unroll
    for (int i = 0; i < 8; i++) vtot += red[i];
    float inv = rsqrtf(vtot * (1.f/768.f) + 1e-5f);

#pragma unroll
    for (int i = 0; i < 3; i++) {
        int c = tid + 256*i;
        float o = (v[i] - mu) * inv * g[c] + be[c];
        out[row*QD + c] = rnd ? f2tf_f(o) : o;
    }
}

// smem byte sizes per instantiation
template<int BM, int BN, bool TRB, int STG>
constexpr int smem_bytes() {
    return STG * (BM*36 + (TRB ? BN*36 : 32*(BN+8))) * 4;
}

extern "C" void kernel_launch(void* const* d_in, const int* in_sizes, int n_in,
                              void* d_out_v, int out_size)
{
    const float* expert = (const float*)d_in[0];
    const float* kv     = (const float*)d_in[1];
    const float* WQ  = (const float*)d_in[2];
    const float* bQ  = (const float*)d_in[3];
    const float* WK  = (const float*)d_in[4];
    const float* bK  = (const float*)d_in[5];
    const float* WV  = (const float*)d_in[6];
    const float* bV  = (const float*)d_in[7];
    const float* W1  = (const float*)d_in[8];
    const float* b1  = (const float*)d_in[9];
    const float* W2  = (const float*)d_in[10];
    const float* b2  = (const float*)d_in[11];
    const float* g1  = (const float*)d_in[12];
    const float* be1 = (const float*)d_in[13];
    const float* g2  = (const float*)d_in[14];
    const float* be2 = (const float*)d_in[15];

    float* out   = (float*)d_out_v;
    float* attnw = out + ((long)out_size - (long)NATTN);

    float *Q, *qb, *Qt, *ctx, *ao, *x, *hid, *y;
    cudaGetSymbolAddress((void**)&Q,   g_Q);
    cudaGetSymbolAddress((void**)&qb,  g_qb);
    cudaGetSymbolAddress((void**)&Qt,  g_Qt);
    cudaGetSymbolAddress((void**)&ctx, g_ctx);
    cudaGetSymbolAddress((void**)&ao,  g_ao);
    cudaGetSymbolAddress((void**)&x,   g_x);
    cudaGetSymbolAddress((void**)&hid, g_hid);
    cudaGetSymbolAddress((void**)&y,   g_y);

    // 1) Q proj (NN, warp 32x32, 3-stage, MINB 2): Q -> RND
    cudaFuncSetAttribute(mma_gemm<32,128,32,false,1,true,true,true,3,2>,
        cudaFuncAttributeMaxDynamicSharedMemorySize, smem_bytes<32,128,false,3>());
    mma_gemm<32,128,32,false,1,true,true,true,3,2>
        <<<dim3(QD/128, 1, TT), 128, smem_bytes<32,128,false,3>()>>>(
        expert, TT*QD, (long)QD,
        WQ, QD, (long)QD*QD,
        Q, TT*QD, (long)QD,
        bQ, QD, BB, 1.f, QD);

    // 2) qb = per-head Q . bK
    qb_k<<<(BT_ROWS*HH)/256, 256>>>(Q, bK, qb);

    // 3) Qt = Q @ WK^T (NT, nk=2, warp 64x32, 2-stage, MINB 3); Qt -> RND
    cudaFuncSetAttribute(mma_gemm<64,128,64,true,0,false,true,true,2,3>,
        cudaFuncAttributeMaxDynamicSharedMemorySize, smem_bytes<64,128,true,2>());
    mma_gemm<64,128,64,true,0,false,true,true,2,3>
        <<<dim3(KVD/128, 7, HH), 128, smem_bytes<64,128,true,2>()>>>(
        Q, QD, (long)HD,
        WK, QD, (long)HD,
        Qt, HH*KVD, (long)KVD,
        nullptr, 0, BT_ROWS, 1.f, HD);

    // 4) scores = (Qt . kv + qb)/8  (NT, warp 64x32, 2-stage + 3 CTA/SM)
    cudaFuncSetAttribute(mma_gemm<64,128,64,true,3,false,true,false,2,3>,
        cudaFuncAttributeMaxDynamicSharedMemorySize, smem_bytes<64,128,true,2>());
    mma_gemm<64,128,64,true,3,false,true,false,2,3>
        <<<dim3(MM/128, 3, BB), 128, smem_bytes<64,128,true,2>()>>>(
        Qt, KVD, (long)RH*KVD,
        kv, KVD, (long)MM*KVD,
        attnw, MM, (long)RH*MM,
        qb, RH, RH, 0.125f, KVD);

    // 5) softmax over m (in place; FMA-pipe exp; rounds attnw to tf32-nearest)
    softmax_k<<<BB*TT*HH, 256>>>(attnw);

    // 6) ctx = attnw . kv  (NN, warp 64x32, 2-stage + 3 CTA/SM); ctx -> RND
    cudaFuncSetAttribute(mma_gemm<64,128,64,false,0,false,true,true,2,3>,
        cudaFuncAttributeMaxDynamicSharedMemorySize, smem_bytes<64,128,false,2>());
    mma_gemm<64,128,64,false,0,false,true,true,2,3>
        <<<dim3(KVD/128, 3, BB), 128, smem_bytes<64,128,false,2>()>>>(
        attnw, MM, (long)RH*MM,
        kv, KVD, (long)MM*KVD,
        ctx, KVD, (long)RH*KVD,
        nullptr, 0, RH, 1.f, MM);

    // 7) attn_out = ctx @ WV + bV  (small; warp 64x32, 3-stage, MINB 2)
    cudaFuncSetAttribute(mma_gemm<64,64,64,false,1,false,true,false,3,2>,
        cudaFuncAttributeMaxDynamicSharedMemorySize, smem_bytes<64,64,false,3>());
    mma_gemm<64,64,64,false,1,false,true,false,3,2>
        <<<dim3(1, 7, HH), 64, smem_bytes<64,64,false,3>()>>>(
        ctx, HH*KVD, (long)KVD,
        WV, QD, (long)HD,
        ao, QD, (long)HD,
        bV, HD, BT_ROWS, 1.f, KVD);

    // 8) x = LN1(expert + attn_out), rounded (x feeds FF1 as A)
    ln_k<<<BT_ROWS, 256>>>(expert, ao, g1, be1, x, 1);

    // 9) hidden = relu(x @ W1 + b1)  (NN, warp 64x32, 3-stage, MINB 2); hid -> RND
    cudaFuncSetAttribute(mma_gemm<64,128,64,false,2,false,true,true,3,2>,
        cudaFuncAttributeMaxDynamicSharedMemorySize, smem_bytes<64,128,false,3>());
    mma_gemm<64,128,64,false,2,false,true,true,3,2>
        <<<dim3(FFD/128, 7, 1), 128, smem_bytes<64,128,false,3>()>>>(
        x, QD, 0,
        W1, FFD, 0,
        hid, FFD, 0,
        b1, 0, BT_ROWS, 1.f, QD);

    // 10) y = hid @ W2 + b2  (NN, warp 64x32, 3-stage, MINB 2)
    cudaFuncSetAttribute(mma_gemm<64,128,64,false,1,false,true,false,3,2>,
        cudaFuncAttributeMaxDynamicSharedMemorySize, smem_bytes<64,128,false,3>());
    mma_gemm<64,128,64,false,1,false,true,false,3,2>
        <<<dim3(QD/128, 7, 1), 128, smem_bytes<64,128,false,3>()>>>(
        hid, FFD, 0,
        W2, QD, 0,
        y, QD, 0,
        b2, 0, BT_ROWS, 1.f, FFD);

    // 11) out = LN2(x + y), full precision (checked output)
    ln_k<<<BT_ROWS, 256>>>(x, y, g2, be2, out, 0);
}

// round 17
// speedup vs baseline: 1.1357x; 1.0662x over previous
#include <cuda_runtime.h>
#include <math.h>
#include <stdint.h>

// Problem dims
#define BB   32
#define TT   14
#define MM   2048
#define QD   768
#define KVD  1024
#define HH   12
#define HD   64
#define FFD  3072
#define BT_ROWS 448   // B*T
#define RH      168   // T*H
#define NATTN (BB*TT*HH*MM)   // 11010048

// -------- scratch (device globals; no allocation allowed) --------
__device__ float g_Q  [BT_ROWS*QD];
__device__ float g_qb [BT_ROWS*HH];
__device__ float g_Qt [BT_ROWS*HH*KVD];
__device__ float g_ctx[BT_ROWS*HH*KVD];
__device__ float g_ao [BT_ROWS*QD];
__device__ float g_x  [BT_ROWS*QD];
__device__ float g_hid[BT_ROWS*FFD];
__device__ float g_y  [BT_ROWS*QD];

__device__ __forceinline__ uint32_t f2tf_u(float f) {
    uint32_t r;
    asm("cvt.rna.tf32.f32 %0, %1;" : "=r"(r) : "f"(f));
    return r;
}
__device__ __forceinline__ float f2tf_f(float f) {
    return __uint_as_float(f2tf_u(f));
}

__device__ __forceinline__ void cp16(uint32_t dst, const float* src, bool pred) {
    asm volatile("cp.async.cg.shared.global [%0], [%1], 16, %2;"
                 :: "r"(dst), "l"(src), "r"(pred ? 16 : 0));
}
__device__ __forceinline__ void cp_commit() {
    asm volatile("cp.async.commit_group;" ::: "memory");
}
__device__ __forceinline__ void cp_wait0() {
    asm volatile("cp.async.wait_group 0;" ::: "memory");
}
__device__ __forceinline__ void cp_wait1() {
    asm volatile("cp.async.wait_group 1;" ::: "memory");
}

// ============================================================================
// TF32 tensor-core GEMM, BK=32, cp.async pipeline with per-call-site depth.
//   STG:  2 = double buffer (wait0, dist 1), 3 = triple buffer (wait1, dist 2)
//   MINB: min-blocks residency hint (3 -> interleave CTA phases)
//   BM=96/WM=96 variant (MC=6) cuts kv L2 re-reads on the attention GEMMs
//   (grid y 3 -> 2 over RH=168 rows).
//   C[m,n] = sum_k A[m,k] * B'[k,n]  (per batch z)
//   TRB=false: B'[k,n] = Bp[k*ldb + n]   ("NN")
//   TRB=true : B'[k,n] = Bp[n*ldb + k]   ("NT")
// EPI: 0=none, 1=+colbias, 2=relu(+colbias), 3=(acc+rowbias)*scale
// CVTA/CVTB: round fragments to tf32-nearest in-loop. RND: round outputs.
// Warp tile WM x 32. K%32==0, N%BN==0; M guarded.
// ============================================================================
template<int BM, int BN, int WM, bool TRB, int EPI, bool CVTA, bool CVTB, bool RND,
         int STG, int MINB>
__global__ void __launch_bounds__((BM/WM)*(BN/32)*32, MINB)
mma_gemm(const float* __restrict__ A, int lda, long aBS,
         const float* __restrict__ Bp, int ldb, long bBS,
         float* __restrict__ C, int ldc, long cBS,
         const float* __restrict__ bias, int biasBS,
         int Mrows, float scale, int K)
{
    constexpr int NWARP = (BM/WM)*(BN/32);
    constexpr int NTH   = NWARP*32;
    constexpr int AST   = BM*36;                    // floats per A stage
    constexpr int BST   = TRB ? BN*36 : 32*(BN+8);  // floats per B stage
    constexpr int MC    = WM/16;                    // 16-row chunks per warp

    extern __shared__ float smem[];
    float* As = smem;                               // STG stages
    float* Bs = smem + STG*AST;
    uint32_t s_as = (uint32_t)__cvta_generic_to_shared(As);
    uint32_t s_bs = (uint32_t)__cvta_generic_to_shared(Bs);

    const int bz = blockIdx.z;
    A  += (long)bz * aBS;
    Bp += (long)bz * bBS;
    C  += (long)bz * cBS;
    if (bias) bias += (long)bz * biasBS;

    const int row0 = blockIdx.y * BM;
    const int col0 = blockIdx.x * BN;
    const int tid  = threadIdx.x;
    const int lane = tid & 31;
    const int warp = tid >> 5;
    const int wm   = warp / (BN/32);
    const int wn   = warp % (BN/32);
    const int g    = lane >> 2;
    const int tg   = lane & 3;

    auto stage_load = [&](int st, int k0) {
#pragma unroll
        for (int it = 0; it < (BM*8)/NTH; it++) {
            int i = tid + it*NTH;
            int m = i >> 3, q = i & 7;
            cp16(s_as + (uint32_t)(st*AST + m*36 + q*4)*4,
                 A + (long)(row0+m)*lda + k0 + q*4,
                 (row0 + m) < Mrows);
        }
        if (TRB) {
#pragma unroll
            for (int it = 0; it < (BN*8)/NTH; it++) {
                int i = tid + it*NTH;
                int n = i >> 3, q = i & 7;
                cp16(s_bs + (uint32_t)(st*BST + n*36 + q*4)*4,
                     Bp + (long)(col0+n)*ldb + k0 + q*4, true);
            }
        } else {
#pragma unroll
            for (int it = 0; it < (32*(BN/4))/NTH; it++) {
                int i = tid + it*NTH;
                int k = i / (BN/4), nq = i % (BN/4);
                cp16(s_bs + (uint32_t)(st*BST + k*(BN+8) + nq*4)*4,
                     Bp + (long)(k0+k)*ldb + col0 + nq*4, true);
            }
        }
    };

    float acc[MC][4][4];
#pragma unroll
    for (int i = 0; i < MC; i++)
#pragma unroll
        for (int j = 0; j < 4; j++)
#pragma unroll
            for (int r = 0; r < 4; r++) acc[i][j][r] = 0.f;

    const int nk = K/32;
    stage_load(0, 0);
    cp_commit();
    if (STG == 3) {
        if (nk > 1) stage_load(1, 32);
        cp_commit();
    }

    for (int t = 0; t < nk; t++) {
        if (STG == 3) cp_wait1(); else cp_wait0();
        __syncthreads();
        if (STG == 3) {
            if (t + 2 < nk) stage_load((t+2)%3, (t+2)*32);
            cp_commit();
        } else {
            if (t + 1 < nk) { stage_load((t+1)&1, (t+1)*32); cp_commit(); }
        }

        const float* As_s = As + (STG == 3 ? (t%3) : (t&1))*AST;
        const float* Bs_s = Bs + (STG == 3 ? (t%3) : (t&1))*BST;

#pragma unroll
        for (int kk = 0; kk < 4; kk++) {
            uint32_t a[MC][4];
#pragma unroll
            for (int i = 0; i < MC; i++) {
                int r = wm*WM + i*16;
                float a0 = As_s[(r+g  )*36 + kk*8 + tg  ];
                float a1 = As_s[(r+g+8)*36 + kk*8 + tg  ];
                float a2 = As_s[(r+g  )*36 + kk*8 + tg+4];
                float a3 = As_s[(r+g+8)*36 + kk*8 + tg+4];
                a[i][0] = CVTA ? f2tf_u(a0) : __float_as_uint(a0);
                a[i][1] = CVTA ? f2tf_u(a1) : __float_as_uint(a1);
                a[i][2] = CVTA ? f2tf_u(a2) : __float_as_uint(a2);
                a[i][3] = CVTA ? f2tf_u(a3) : __float_as_uint(a3);
            }
            uint32_t b[4][2];
#pragma unroll
            for (int j = 0; j < 4; j++) {
                int n = wn*32 + j*8 + g;
                float b0, b1;
                if (TRB) {
                    b0 = Bs_s[n*36 + kk*8 + tg  ];
                    b1 = Bs_s[n*36 + kk*8 + tg+4];
                } else {
                    b0 = Bs_s[(kk*8 + tg  )*(BN+8) + n];
                    b1 = Bs_s[(kk*8 + tg+4)*(BN+8) + n];
                }
                b[j][0] = CVTB ? f2tf_u(b0) : __float_as_uint(b0);
                b[j][1] = CVTB ? f2tf_u(b1) : __float_as_uint(b1);
            }
#pragma unroll
            for (int i = 0; i < MC; i++)
#pragma unroll
                for (int j = 0; j < 4; j++) {
                    asm volatile(
                        "mma.sync.aligned.m16n8k8.row.col.f32.tf32.tf32.f32 "
                        "{%0,%1,%2,%3}, {%4,%5,%6,%7}, {%8,%9}, {%0,%1,%2,%3};"
                        : "+f"(acc[i][j][0]), "+f"(acc[i][j][1]),
                          "+f"(acc[i][j][2]), "+f"(acc[i][j][3])
                        : "r"(a[i][0]), "r"(a[i][1]), "r"(a[i][2]), "r"(a[i][3]),
                          "r"(b[j][0]), "r"(b[j][1]));
                }
        }
    }

    // ---- epilogue ----
#pragma unroll
    for (int i = 0; i < MC; i++) {
        int r0 = row0 + wm*WM + i*16 + g;
#pragma unroll
        for (int rr = 0; rr < 2; rr++) {
            int gm = r0 + rr*8;
            if (gm >= Mrows) continue;
            float rb = (EPI == 3) ? bias[gm] : 0.f;
#pragma unroll
            for (int j = 0; j < 4; j++) {
                int cn = col0 + wn*32 + j*8 + 2*tg;
                float v0 = acc[i][j][rr*2 + 0];
                float v1 = acc[i][j][rr*2 + 1];
                if (EPI == 1)      { v0 += bias[cn]; v1 += bias[cn+1]; }
                else if (EPI == 2) { v0 = fmaxf(v0 + bias[cn], 0.f);
                                     v1 = fmaxf(v1 + bias[cn+1], 0.f); }
                else if (EPI == 3) { v0 = (v0 + rb) * scale; v1 = (v1 + rb) * scale; }
                if (RND) { v0 = f2tf_f(v0); v1 = f2tf_f(v1); }
                *(float2*)(C + (long)gm*ldc + cn) = make_float2(v0, v1);
            }
        }
    }
}

// qb[bt,h] = sum_d Q[bt, h*64+d] * bK[h*64+d]
__global__ void qb_k(const float* __restrict__ Q, const float* __restrict__ bK,
                     float* __restrict__ qb)
{
    int idx = blockIdx.x*blockDim.x + threadIdx.x;
    if (idx >= BT_ROWS*HH) return;
    int bt = idx / HH, h = idx % HH;
    const float* q  = Q  + (long)bt*QD + h*HD;
    const float* bk = bK + h*HD;
    float s = 0.f;
#pragma unroll 8
    for (int d = 0; d < HD; d++) s = fmaf(q[d], bk[d], s);
    qb[idx] = s;
}

// in-place softmax over rows of length 2048 (DRAM-bound; __expf is fine).
// Output rounded to tf32-nearest (attnw feeds the ctx GEMM as A operand).
__global__ void softmax_k(float* __restrict__ attn)
{
    float* p = attn + (long)blockIdx.x * MM;
    int tid = threadIdx.x;
    int lane = tid & 31, w = tid >> 5;
    __shared__ float red[8];

    float v[8];
    float mx = -1e30f;
#pragma unroll
    for (int i = 0; i < 8; i++) { v[i] = p[tid + 256*i]; mx = fmaxf(mx, v[i]); }
#pragma unroll
    for (int o = 16; o; o >>= 1) mx = fmaxf(mx, __shfl_xor_sync(0xffffffffu, mx, o));
    if (lane == 0) red[w] = mx;
    __syncthreads();
    mx = red[0];
#pragma unroll
    for (int i = 1; i < 8; i++) mx = fmaxf(mx, red[i]);
    __syncthreads();

    float s = 0.f;
#pragma unroll
    for (int i = 0; i < 8; i++) { v[i] = __expf(v[i] - mx); s += v[i]; }
#pragma unroll
    for (int o = 16; o; o >>= 1) s += __shfl_xor_sync(0xffffffffu, s, o);
    if (lane == 0) red[w] = s;
    __syncthreads();
    float tot = 0.f;
#pragma unroll
    for (int i = 0; i < 8; i++) tot += red[i];

    float inv = 1.f / tot;
#pragma unroll
    for (int i = 0; i < 8; i++) p[tid + 256*i] = f2tf_f(v[i] * inv);
}

// out[row,:] = LN(a[row,:] + b[row,:]) * g + be   (row length 768)
__global__ void ln_k(const float* __restrict__ a, const float* __restrict__ b,
                     const float* __restrict__ g, const float* __restrict__ be,
                     float* __restrict__ out, int rnd)
{
    long row = blockIdx.x;
    int tid = threadIdx.x;
    int lane = tid & 31, w = tid >> 5;
    const float* pa = a + row*QD;
    const float* pb = b + row*QD;
    __shared__ float red[8];

    float v[3];
    float s = 0.f;
#pragma unroll
    for (int i = 0; i < 3; i++) { v[i] = pa[tid + 256*i] + pb[tid + 256*i]; s += v[i]; }
#pragma unroll
    for (int o = 16; o; o >>= 1) s += __shfl_xor_sync(0xffffffffu, s, o);
    if (lane == 0) red[w] = s;
    __syncthreads();
    float tot = 0.f;
#pragma unroll
    for (int i = 0; i < 8; i++) tot += red[i];
    float mu = tot * (1.f/768.f);
    __syncthreads();

    float sq = 0.f;
#pragma unroll
    for (int i = 0; i < 3; i++) { float d = v[i] - mu; sq = fmaf(d, d, sq); }
#pragma unroll
    for (int o = 16; o; o >>= 1) sq += __shfl_xor_sync(0xffffffffu, sq, o);
    if (lane == 0) red[w] = sq;
    __syncthreads();
    float vtot = 0.f;
#pragma unroll
    for (int i = 0; i < 8; i++) vtot += red[i];
    float inv = rsqrtf(vtot * (1.f/768.f) + 1e-5f);

#pragma unroll
    for (int i = 0; i < 3; i++) {
        int c = tid + 256*i;
        float o = (v[i] - mu) * inv * g[c] + be[c];
        out[row*QD + c] = rnd ? f2tf_f(o) : o;
    }
}

// smem byte sizes per instantiation
template<int BM, int BN, bool TRB, int STG>
constexpr int smem_bytes() {
    return STG * (BM*36 + (TRB ? BN*36 : 32*(BN+8))) * 4;
}

extern "C" void kernel_launch(void* const* d_in, const int* in_sizes, int n_in,
                              void* d_out_v, int out_size)
{
    const float* expert = (const float*)d_in[0];
    const float* kv     = (const float*)d_in[1];
    const float* WQ  = (const float*)d_in[2];
    const float* bQ  = (const float*)d_in[3];
    const float* WK  = (const float*)d_in[4];
    const float* bK  = (const float*)d_in[5];
    const float* WV  = (const float*)d_in[6];
    const float* bV  = (const float*)d_in[7];
    const float* W1  = (const float*)d_in[8];
    const float* b1  = (const float*)d_in[9];
    const float* W2  = (const float*)d_in[10];
    const float* b2  = (const float*)d_in[11];
    const float* g1  = (const float*)d_in[12];
    const float* be1 = (const float*)d_in[13];
    const float* g2  = (const float*)d_in[14];
    const float* be2 = (const float*)d_in[15];

    float* out   = (float*)d_out_v;
    float* attnw = out + ((long)out_size - (long)NATTN);

    float *Q, *qb, *Qt, *ctx, *ao, *x, *hid, *y;
    cudaGetSymbolAddress((void**)&Q,   g_Q);
    cudaGetSymbolAddress((void**)&qb,  g_qb);
    cudaGetSymbolAddress((void**)&Qt,  g_Qt);
    cudaGetSymbolAddress((void**)&ctx, g_ctx);
    cudaGetSymbolAddress((void**)&ao,  g_ao);
    cudaGetSymbolAddress((void**)&x,   g_x);
    cudaGetSymbolAddress((void**)&hid, g_hid);
    cudaGetSymbolAddress((void**)&y,   g_y);

    // 1) Q proj (NN, warp 32x32, 3-stage, MINB 2): Q -> RND
    cudaFuncSetAttribute(mma_gemm<32,128,32,false,1,true,true,true,3,2>,
        cudaFuncAttributeMaxDynamicSharedMemorySize, smem_bytes<32,128,false,3>());
    mma_gemm<32,128,32,false,1,true,true,true,3,2>
        <<<dim3(QD/128, 1, TT), 128, smem_bytes<32,128,false,3>()>>>(
        expert, TT*QD, (long)QD,
        WQ, QD, (long)QD*QD,
        Q, TT*QD, (long)QD,
        bQ, QD, BB, 1.f, QD);

    // 2) qb = per-head Q . bK
    qb_k<<<(BT_ROWS*HH)/256, 256>>>(Q, bK, qb);

    // 3) Qt = Q @ WK^T (NT, nk=2, warp 64x32, 2-stage, MINB 3); Qt -> RND
    cudaFuncSetAttribute(mma_gemm<64,128,64,true,0,false,true,true,2,3>,
        cudaFuncAttributeMaxDynamicSharedMemorySize, smem_bytes<64,128,true,2>());
    mma_gemm<64,128,64,true,0,false,true,true,2,3>
        <<<dim3(KVD/128, 7, HH), 128, smem_bytes<64,128,true,2>()>>>(
        Q, QD, (long)HD,
        WK, QD, (long)HD,
        Qt, HH*KVD, (long)KVD,
        nullptr, 0, BT_ROWS, 1.f, HD);

    // 4) scores = (Qt . kv + qb)/8  (NT, BM=96 -> grid y=2, kv read 2x not 3x)
    cudaFuncSetAttribute(mma_gemm<96,128,96,true,3,false,true,false,2,3>,
        cudaFuncAttributeMaxDynamicSharedMemorySize, smem_bytes<96,128,true,2>());
    mma_gemm<96,128,96,true,3,false,true,false,2,3>
        <<<dim3(MM/128, 2, BB), 128, smem_bytes<96,128,true,2>()>>>(
        Qt, KVD, (long)RH*KVD,
        kv, KVD, (long)MM*KVD,
        attnw, MM, (long)RH*MM,
        qb, RH, RH, 0.125f, KVD);

    // 5) softmax over m (in place; rounds attnw to tf32-nearest)
    softmax_k<<<BB*TT*HH, 256>>>(attnw);

    // 6) ctx = attnw . kv  (NN, BM=96 -> grid y=2); ctx -> RND
    cudaFuncSetAttribute(mma_gemm<96,128,96,false,0,false,true,true,2,3>,
        cudaFuncAttributeMaxDynamicSharedMemorySize, smem_bytes<96,128,false,2>());
    mma_gemm<96,128,96,false,0,false,true,true,2,3>
        <<<dim3(KVD/128, 2, BB), 128, smem_bytes<96,128,false,2>()>>>(
        attnw, MM, (long)RH*MM,
        kv, KVD, (long)MM*KVD,
        ctx, KVD, (long)RH*KVD,
        nullptr, 0, RH, 1.f, MM);

    // 7) attn_out = ctx @ WV + bV  (small; warp 64x32, 3-stage, MINB 2)
    cudaFuncSetAttribute(mma_gemm<64,64,64,false,1,false,true,false,3,2>,
        cudaFuncAttributeMaxDynamicSharedMemorySize, smem_bytes<64,64,false,3>());
    mma_gemm<64,64,64,false,1,false,true,false,3,2>
        <<<dim3(1, 7, HH), 64, smem_bytes<64,64,false,3>()>>>(
        ctx, HH*KVD, (long)KVD,
        WV, QD, (long)HD,
        ao, QD, (long)HD,
        bV, HD, BT_ROWS, 1.f, KVD);

    // 8) x = LN1(expert + attn_out), rounded (x feeds FF1 as A)
    ln_k<<<BT_ROWS, 256>>>(expert, ao, g1, be1, x, 1);

    // 9) hidden = relu(x @ W1 + b1)  (NN, warp 64x32, 3-stage, MINB 2); hid -> RND
    cudaFuncSetAttribute(mma_gemm<64,128,64,false,2,false,true,true,3,2>,
        cudaFuncAttributeMaxDynamicSharedMemorySize, smem_bytes<64,128,false,3>());
    mma_gemm<64,128,64,false,2,false,true,true,3,2>
        <<<dim3(FFD/128, 7, 1), 128, smem_bytes<64,128,false,3>()>>>(
        x, QD, 0,
        W1, FFD, 0,
        hid, FFD, 0,
        b1, 0, BT_ROWS, 1.f, QD);

    // 10) y = hid @ W2 + b2  (NN, warp 64x32, 3-stage, MINB 2)
    cudaFuncSetAttribute(mma_gemm<64,128,64,false,1,false,true,false,3,2>,
        cudaFuncAttributeMaxDynamicSharedMemorySize, smem_bytes<64,128,false,3>());
    mma_gemm<64,128,64,false,1,false,true,false,3,2>
        <<<dim3(QD/128, 7, 1), 128, smem_bytes<64,128,false,3>()>>>(
        hid, FFD, 0,
        W2, QD, 0,
        y, QD, 0,
        b2, 0, BT_ROWS, 1.f, FFD);

    // 11) out = LN2(x + y), full precision (checked output)
    ln_k<<<BT_ROWS, 256>>>(x, y, g2, be2, out, 0);
}